// round 11
// baseline (speedup 1.0000x reference)
#include <cuda_runtime.h>

// Problem constants
#define NB   512      // batches
#define NL   512      // stream length
#define NC   8        // channels
#define NSEG 8        // segments per batch (Chen-associative split)
#define SEGLEN 64     // increments per segment (last has 63)
#define SIGSZ 584     // 8 + 64 + 512
#define NINC (NL - 1) // 511
#define SBUF 592      // padded per-warp smem buffer (>= 584 and >= SEGLEN*NC)

// Scratch: per-batch half signatures [batch][half][584] = 2.39 MB (L2-resident)
__device__ float g_half[(size_t)NB * 2 * SIGSZ];

// ---------------------------------------------------------------------------
// Scan kernel: 1024 blocks x 128 threads; block = (batch, half), 4 warps =
// 4 segments of 64 steps. Lane owns pairs (i,j0),(i,j0+1): i=lane>>2,
// j0=(lane&3)*2. Per step (old state RHS), m/n shared across the pair:
//   m = dxi/6 + S1h ; n = 3m - S1h (= dxi/2 + S1)
//   c_p = dxj_p*m + S2_p ; S2_p += dxj_p*n ; S3[p][k] += c_p*dx_k ; S1h += dxi/2
// Then 2-round in-block tree fold -> half-signature to g_half.
// ---------------------------------------------------------------------------

struct SigRegs {
    float A1;        // A1[i]
    float A2[2];     // A2[i,j0], A2[i,j0+1]
    float A3[2][8];  // A3[i,j0,:], A3[i,j0+1,:]
};

// store in standard sig layout (works for smem or gmem)
__device__ __forceinline__ void sig_store(float* __restrict__ sb,
                                          const SigRegs& S, int i, int j0) {
    if (j0 == 0) sb[i] = S.A1;
    *(float2*)(sb + 8 + i * 8 + j0) = make_float2(S.A2[0], S.A2[1]);
    float* b3 = sb + 72 + (i * 8 + j0) * 8;
    *(float4*)(b3)      = make_float4(S.A3[0][0], S.A3[0][1], S.A3[0][2], S.A3[0][3]);
    *(float4*)(b3 + 4)  = make_float4(S.A3[0][4], S.A3[0][5], S.A3[0][6], S.A3[0][7]);
    *(float4*)(b3 + 8)  = make_float4(S.A3[1][0], S.A3[1][1], S.A3[1][2], S.A3[1][3]);
    *(float4*)(b3 + 12) = make_float4(S.A3[1][4], S.A3[1][5], S.A3[1][6], S.A3[1][7]);
}

// Chen fold, 2-pair layout (B in standard sig layout; old A on RHS)
__device__ __forceinline__ void sig_fold(SigRegs& S, const float* __restrict__ sb,
                                         int i, int j0) {
    const float B1i = sb[i];
    const float2 B1j  = *(const float2*)(sb + j0);
    const float2 B2ij = *(const float2*)(sb + 8 + i * 8 + j0);
    float4 x0 = *(const float4*)(sb);
    float4 x1 = *(const float4*)(sb + 4);
    float4 y0 = *(const float4*)(sb + 8 + j0 * 8);
    float4 y1 = *(const float4*)(sb + 8 + j0 * 8 + 4);
    float4 y2 = *(const float4*)(sb + 8 + j0 * 8 + 8);
    float4 y3 = *(const float4*)(sb + 8 + j0 * 8 + 12);
    const float* b3p = sb + 72 + (i * 8 + j0) * 8;
    float4 z0 = *(const float4*)(b3p);
    float4 z1 = *(const float4*)(b3p + 4);
    float4 z2 = *(const float4*)(b3p + 8);
    float4 z3 = *(const float4*)(b3p + 12);

    float b1v[8]    = {x0.x, x0.y, x0.z, x0.w, x1.x, x1.y, x1.z, x1.w};
    float b2v[2][8] = {{y0.x, y0.y, y0.z, y0.w, y1.x, y1.y, y1.z, y1.w},
                       {y2.x, y2.y, y2.z, y2.w, y3.x, y3.y, y3.z, y3.w}};
    float b3v[2][8] = {{z0.x, z0.y, z0.z, z0.w, z1.x, z1.y, z1.z, z1.w},
                       {z2.x, z2.y, z2.z, z2.w, z3.x, z3.y, z3.z, z3.w}};

    #pragma unroll
    for (int p = 0; p < 2; p++)
        #pragma unroll
        for (int k = 0; k < 8; k++)  // uses OLD A1, A2
            S.A3[p][k] = fmaf(S.A1, b2v[p][k],
                         fmaf(S.A2[p], b1v[k], S.A3[p][k] + b3v[p][k]));
    S.A2[0] = fmaf(S.A1, B1j.x, S.A2[0] + B2ij.x);
    S.A2[1] = fmaf(S.A1, B1j.y, S.A2[1] + B2ij.y);
    S.A1 = S.A1 + B1i;
}

__global__ __launch_bounds__(128, 8) void scan_kernel(const float* __restrict__ path) {
    __shared__ __align__(16) float sdx[4][SBUF];   // 9.5 KB

    const int tid  = threadIdx.x;
    const int g    = tid >> 5;        // warp in block (0..3)
    const int lane = tid & 31;
    const int i    = lane >> 2;
    const int j0   = (lane & 3) << 1;

    const int blk   = blockIdx.x;     // 0..1023
    const int batch = blk >> 1;
    const int half  = blk & 1;
    const int seg   = half * 4 + g;   // global segment 0..7
    const int t0    = seg * SEGLEN;
    const int nsteps = (seg == NSEG - 1) ? (NINC - (NSEG - 1) * SEGLEN) : SEGLEN; // 63/64

    // ---- stage increments (float4) for this warp's segment ----
    {
        const float4* __restrict__ pb4 =
            (const float4*)(path + (size_t)batch * NL * NC + (size_t)t0 * NC);
        float4* __restrict__ s4 = (float4*)sdx[g];
        const int n4 = nsteps * 2;
        for (int v = lane; v < n4; v += 32) {
            float4 a = pb4[v];
            float4 b = pb4[v + 2];   // +8 floats = next step, same chans
            s4[v] = make_float4(b.x - a.x, b.y - a.y, b.z - a.z, b.w - a.w);
        }
    }
    __syncwarp();

    // ---- sequential scan (warp-private) ----
    float S1h = 0.f, S20 = 0.f, S21 = 0.f;
    float S3[2][8];
    #pragma unroll
    for (int p = 0; p < 2; p++)
        #pragma unroll
        for (int k = 0; k < 8; k++) S3[p][k] = 0.f;

    const float* __restrict__ dxp = sdx[g];
    #pragma unroll 4
    for (int s = 0; s < nsteps; s++) {
        const float4 d0 = *(const float4*)(dxp + s * 8);
        const float4 d1 = *(const float4*)(dxp + s * 8 + 4);
        const float  dxi = dxp[s * 8 + i];
        const float2 dxj = *(const float2*)(dxp + s * 8 + j0);

        const float m = fmaf(dxi, 0.16666666666666666f, S1h);
        const float n = fmaf(3.0f, m, -S1h);          // dxi/2 + S1
        const float c0 = fmaf(dxj.x, m, S20);
        const float c1 = fmaf(dxj.y, m, S21);
        S20 = fmaf(dxj.x, n, S20);
        S21 = fmaf(dxj.y, n, S21);

        S3[0][0] = fmaf(c0, d0.x, S3[0][0]);
        S3[0][1] = fmaf(c0, d0.y, S3[0][1]);
        S3[0][2] = fmaf(c0, d0.z, S3[0][2]);
        S3[0][3] = fmaf(c0, d0.w, S3[0][3]);
        S3[0][4] = fmaf(c0, d1.x, S3[0][4]);
        S3[0][5] = fmaf(c0, d1.y, S3[0][5]);
        S3[0][6] = fmaf(c0, d1.z, S3[0][6]);
        S3[0][7] = fmaf(c0, d1.w, S3[0][7]);
        S3[1][0] = fmaf(c1, d0.x, S3[1][0]);
        S3[1][1] = fmaf(c1, d0.y, S3[1][1]);
        S3[1][2] = fmaf(c1, d0.z, S3[1][2]);
        S3[1][3] = fmaf(c1, d0.w, S3[1][3]);
        S3[1][4] = fmaf(c1, d1.x, S3[1][4]);
        S3[1][5] = fmaf(c1, d1.y, S3[1][5]);
        S3[1][6] = fmaf(c1, d1.z, S3[1][6]);
        S3[1][7] = fmaf(c1, d1.w, S3[1][7]);

        S1h = fmaf(0.5f, dxi, S1h);
    }

    SigRegs S;
    S.A1 = 2.f * S1h;
    S.A2[0] = S20; S.A2[1] = S21;
    #pragma unroll
    for (int p = 0; p < 2; p++)
        #pragma unroll
        for (int k = 0; k < 8; k++) S.A3[p][k] = S3[p][k];

    // warp finished reading its own buffer before any publish overwrites it
    __syncwarp();

    // ---- in-block tree fold: 4 segment sigs -> 1 half-signature ----
    if (g & 1) sig_store(sdx[g], S, i, j0);
    __syncthreads();

    // round 1: w0 <- w0 o w1 ; w2 <- w2 o w3 (w2 publishes)
    if ((g & 1) == 0) {
        sig_fold(S, sdx[g + 1], i, j0);
        if (g == 2) sig_store(sdx[2], S, i, j0);
    }
    __syncthreads();

    // round 2: w0 <- w0 o w2 -> write half-signature to scratch
    if (g == 0) {
        sig_fold(S, sdx[2], i, j0);
        sig_store(g_half + (size_t)blk * SIGSZ, S, i, j0);
    }
}

// ---------------------------------------------------------------------------
// Combine kernel: 128 blocks x 256 threads; 64 threads (w=i*8+j) per batch
// perform ONE Chen fold of the two half-signatures. Scratch is L2-hot.
// ---------------------------------------------------------------------------
__global__ __launch_bounds__(256) void combine_kernel(float* __restrict__ out) {
    const int tid = threadIdx.x;
    const int q   = tid >> 6;        // batch slot in block (0..3)
    const int w   = tid & 63;
    const int i   = w >> 3;
    const int j   = w & 7;
    const int batch = blockIdx.x * 4 + q;

    const float* __restrict__ pa = g_half + (size_t)batch * 2 * SIGSZ;  // half 0
    const float* __restrict__ pb = pa + SIGSZ;                          // half 1

    float A1 = pa[i];
    float A2 = pa[8 + w];
    float A3[8];
    {
        float4 a = *(const float4*)(pa + 72 + w * 8);
        float4 b = *(const float4*)(pa + 72 + w * 8 + 4);
        A3[0] = a.x; A3[1] = a.y; A3[2] = a.z; A3[3] = a.w;
        A3[4] = b.x; A3[5] = b.y; A3[6] = b.z; A3[7] = b.w;
    }

    const float B1i  = pb[i];
    const float B1j  = pb[j];
    const float B2ij = pb[8 + w];
    float4 x0 = *(const float4*)(pb);
    float4 x1 = *(const float4*)(pb + 4);
    float4 y0 = *(const float4*)(pb + 8 + j * 8);
    float4 y1 = *(const float4*)(pb + 8 + j * 8 + 4);
    float4 z0 = *(const float4*)(pb + 72 + w * 8);
    float4 z1 = *(const float4*)(pb + 72 + w * 8 + 4);

    float b1v[8] = {x0.x, x0.y, x0.z, x0.w, x1.x, x1.y, x1.z, x1.w};
    float b2v[8] = {y0.x, y0.y, y0.z, y0.w, y1.x, y1.y, y1.z, y1.w};
    float b3v[8] = {z0.x, z0.y, z0.z, z0.w, z1.x, z1.y, z1.z, z1.w};

    #pragma unroll
    for (int k = 0; k < 8; k++)  // uses OLD A1, A2
        A3[k] = fmaf(A1, b2v[k], fmaf(A2, b1v[k], A3[k] + b3v[k]));
    A2 = fmaf(A1, B1j, A2 + B2ij);
    A1 = A1 + B1i;

    float* __restrict__ ob = out + (size_t)batch * SIGSZ;
    if (j == 0) ob[i] = A1;
    ob[8 + w] = A2;
    *(float4*)(ob + 72 + w * 8)     = make_float4(A3[0], A3[1], A3[2], A3[3]);
    *(float4*)(ob + 72 + w * 8 + 4) = make_float4(A3[4], A3[5], A3[6], A3[7]);
}

extern "C" void kernel_launch(void* const* d_in, const int* in_sizes, int n_in,
                              void* d_out, int out_size) {
    const float* path = (const float*)d_in[0];
    float* out = (float*)d_out;
    scan_kernel<<<NB * 2, 128>>>(path);    // 1024 half-batch blocks
    combine_kernel<<<NB / 4, 256>>>(out);  // fold the two halves per batch
}

// round 13
// speedup vs baseline: 1.4221x; 1.4221x over previous
#include <cuda_runtime.h>

// Problem constants
#define NB   512      // batches
#define NL   512      // stream length
#define NC   8        // channels
#define NSEG 8        // segments per batch (Chen-associative split)
#define SEGLEN 64     // increments per segment (last has 63)
#define SIGSZ 584     // 8 + 64 + 512
#define NINC (NL - 1) // 511
#define SBUF 592      // padded per-warp smem buffer (>= 584 and >= SEGLEN*NC)

// Per-half-batch signatures [batch][half][584] (2.39 MB, stays L2-hot)
__device__ float g_half[(size_t)NB * 2 * SIGSZ];
// Per-batch arrival tickets. Zero-initialized once; each kernel launch adds
// exactly 2 per batch, so "second arrival this launch" <=> odd ticket value.
__device__ int g_ticket[NB];

// ---------------------------------------------------------------------------
// One fused kernel: 1024 blocks x 128 threads. Block = (batch, half); its 4
// warps scan 4 consecutive 64-step segments (lane owns pairs (i,j0),(i,j0+1),
// i=lane>>2, j0=(lane&3)*2), tree-fold in smem to a half-batch signature,
// store it, and the LAST block of each batch folds half0 o half1 -> out.
// Chen fold (old A on RHS): S3 += B3 + A1(x)B2 + A2(x)B1; S2 += B2 + A1(x)B1;
// S1 += B1.
// ---------------------------------------------------------------------------

struct SigRegs {
    float A1;        // A1[i]
    float A2[2];     // A2[i,j0], A2[i,j0+1]
    float A3[2][8];  // A3[i,j0,:], A3[i,j0+1,:]
};

__device__ __forceinline__ void sig_store(float* __restrict__ sb,
                                          const SigRegs& S, int i, int j0) {
    if (j0 == 0) sb[i] = S.A1;
    *(float2*)(sb + 8 + i * 8 + j0) = make_float2(S.A2[0], S.A2[1]);
    float* b3 = sb + 72 + (i * 8 + j0) * 8;
    *(float4*)(b3)      = make_float4(S.A3[0][0], S.A3[0][1], S.A3[0][2], S.A3[0][3]);
    *(float4*)(b3 + 4)  = make_float4(S.A3[0][4], S.A3[0][5], S.A3[0][6], S.A3[0][7]);
    *(float4*)(b3 + 8)  = make_float4(S.A3[1][0], S.A3[1][1], S.A3[1][2], S.A3[1][3]);
    *(float4*)(b3 + 12) = make_float4(S.A3[1][4], S.A3[1][5], S.A3[1][6], S.A3[1][7]);
}

// Chen fold with B in shared memory (2-pair layout)
__device__ __forceinline__ void sig_fold(SigRegs& S, const float* __restrict__ sb,
                                         int i, int j0) {
    const float B1i = sb[i];
    const float2 B1j  = *(const float2*)(sb + j0);
    const float2 B2ij = *(const float2*)(sb + 8 + i * 8 + j0);
    float4 x0 = *(const float4*)(sb);
    float4 x1 = *(const float4*)(sb + 4);
    float4 y0 = *(const float4*)(sb + 8 + j0 * 8);
    float4 y1 = *(const float4*)(sb + 8 + j0 * 8 + 4);
    float4 y2 = *(const float4*)(sb + 8 + j0 * 8 + 8);
    float4 y3 = *(const float4*)(sb + 8 + j0 * 8 + 12);
    const float* b3p = sb + 72 + (i * 8 + j0) * 8;
    float4 z0 = *(const float4*)(b3p);
    float4 z1 = *(const float4*)(b3p + 4);
    float4 z2 = *(const float4*)(b3p + 8);
    float4 z3 = *(const float4*)(b3p + 12);

    float b1v[8]    = {x0.x, x0.y, x0.z, x0.w, x1.x, x1.y, x1.z, x1.w};
    float b2v[2][8] = {{y0.x, y0.y, y0.z, y0.w, y1.x, y1.y, y1.z, y1.w},
                       {y2.x, y2.y, y2.z, y2.w, y3.x, y3.y, y3.z, y3.w}};
    float b3v[2][8] = {{z0.x, z0.y, z0.z, z0.w, z1.x, z1.y, z1.z, z1.w},
                       {z2.x, z2.y, z2.z, z2.w, z3.x, z3.y, z3.z, z3.w}};

    #pragma unroll
    for (int p = 0; p < 2; p++)
        #pragma unroll
        for (int k = 0; k < 8; k++)  // uses OLD A1, A2
            S.A3[p][k] = fmaf(S.A1, b2v[p][k],
                         fmaf(S.A2[p], b1v[k], S.A3[p][k] + b3v[p][k]));
    S.A2[0] = fmaf(S.A1, B1j.x, S.A2[0] + B2ij.x);
    S.A2[1] = fmaf(S.A1, B1j.y, S.A2[1] + B2ij.y);
    S.A1 = S.A1 + B1i;
}

// Load a signature from global into regs (L2 path, bypass L1 for freshness)
__device__ __forceinline__ void sig_load_cg(SigRegs& S, const float* __restrict__ p,
                                            int i, int j0) {
    S.A1 = __ldcg(p + i);
    float2 a2 = __ldcg((const float2*)(p + 8 + i * 8 + j0));
    S.A2[0] = a2.x; S.A2[1] = a2.y;
    const float* b3 = p + 72 + (i * 8 + j0) * 8;
    float4 z0 = __ldcg((const float4*)(b3));
    float4 z1 = __ldcg((const float4*)(b3 + 4));
    float4 z2 = __ldcg((const float4*)(b3 + 8));
    float4 z3 = __ldcg((const float4*)(b3 + 12));
    S.A3[0][0]=z0.x; S.A3[0][1]=z0.y; S.A3[0][2]=z0.z; S.A3[0][3]=z0.w;
    S.A3[0][4]=z1.x; S.A3[0][5]=z1.y; S.A3[0][6]=z1.z; S.A3[0][7]=z1.w;
    S.A3[1][0]=z2.x; S.A3[1][1]=z2.y; S.A3[1][2]=z2.z; S.A3[1][3]=z2.w;
    S.A3[1][4]=z3.x; S.A3[1][5]=z3.y; S.A3[1][6]=z3.z; S.A3[1][7]=z3.w;
}

// Chen fold with B in global memory via __ldcg (2-pair layout)
__device__ __forceinline__ void sig_fold_cg(SigRegs& S, const float* __restrict__ sb,
                                            int i, int j0) {
    const float B1i = __ldcg(sb + i);
    const float2 B1j  = __ldcg((const float2*)(sb + j0));
    const float2 B2ij = __ldcg((const float2*)(sb + 8 + i * 8 + j0));
    float4 x0 = __ldcg((const float4*)(sb));
    float4 x1 = __ldcg((const float4*)(sb + 4));
    float4 y0 = __ldcg((const float4*)(sb + 8 + j0 * 8));
    float4 y1 = __ldcg((const float4*)(sb + 8 + j0 * 8 + 4));
    float4 y2 = __ldcg((const float4*)(sb + 8 + j0 * 8 + 8));
    float4 y3 = __ldcg((const float4*)(sb + 8 + j0 * 8 + 12));
    const float* b3p = sb + 72 + (i * 8 + j0) * 8;
    float4 z0 = __ldcg((const float4*)(b3p));
    float4 z1 = __ldcg((const float4*)(b3p + 4));
    float4 z2 = __ldcg((const float4*)(b3p + 8));
    float4 z3 = __ldcg((const float4*)(b3p + 12));

    float b1v[8]    = {x0.x, x0.y, x0.z, x0.w, x1.x, x1.y, x1.z, x1.w};
    float b2v[2][8] = {{y0.x, y0.y, y0.z, y0.w, y1.x, y1.y, y1.z, y1.w},
                       {y2.x, y2.y, y2.z, y2.w, y3.x, y3.y, y3.z, y3.w}};
    float b3v[2][8] = {{z0.x, z0.y, z0.z, z0.w, z1.x, z1.y, z1.z, z1.w},
                       {z2.x, z2.y, z2.z, z2.w, z3.x, z3.y, z3.z, z3.w}};

    #pragma unroll
    for (int p = 0; p < 2; p++)
        #pragma unroll
        for (int k = 0; k < 8; k++)
            S.A3[p][k] = fmaf(S.A1, b2v[p][k],
                         fmaf(S.A2[p], b1v[k], S.A3[p][k] + b3v[p][k]));
    S.A2[0] = fmaf(S.A1, B1j.x, S.A2[0] + B2ij.x);
    S.A2[1] = fmaf(S.A1, B1j.y, S.A2[1] + B2ij.y);
    S.A1 = S.A1 + B1i;
}

__global__ __launch_bounds__(128) void sig_kernel(const float* __restrict__ path,
                                                  float* __restrict__ out) {
    __shared__ __align__(16) float sdx[4][SBUF];   // 9.5 KB

    const int tid  = threadIdx.x;
    const int g    = tid >> 5;        // warp in block (0..3)
    const int lane = tid & 31;
    const int i    = lane >> 2;
    const int j0   = (lane & 3) << 1;

    const int blk   = blockIdx.x;     // 0..1023
    const int batch = blk >> 1;
    const int half  = blk & 1;
    const int seg   = half * 4 + g;   // global segment 0..7
    const int t0    = seg * SEGLEN;
    const int nsteps = (seg == NSEG - 1) ? (NINC - (NSEG - 1) * SEGLEN) : SEGLEN; // 63/64

    // ---- stage increments (float4) for this warp's segment ----
    {
        const float4* __restrict__ pb4 =
            (const float4*)(path + (size_t)batch * NL * NC + (size_t)t0 * NC);
        float4* __restrict__ s4 = (float4*)sdx[g];
        const int n4 = nsteps * 2;
        for (int v = lane; v < n4; v += 32) {
            float4 a = pb4[v];
            float4 b = pb4[v + 2];   // +8 floats = next step, same chans
            s4[v] = make_float4(b.x - a.x, b.y - a.y, b.z - a.z, b.w - a.w);
        }
    }
    __syncwarp();

    // ---- sequential scan (warp-private) ----
    float S1h = 0.f, S20 = 0.f, S21 = 0.f;
    float S3[2][8];
    #pragma unroll
    for (int p = 0; p < 2; p++)
        #pragma unroll
        for (int k = 0; k < 8; k++) S3[p][k] = 0.f;

    const float* __restrict__ dxp = sdx[g];
    #pragma unroll 4
    for (int s = 0; s < nsteps; s++) {
        const float4 d0 = *(const float4*)(dxp + s * 8);
        const float4 d1 = *(const float4*)(dxp + s * 8 + 4);
        const float  dxi = dxp[s * 8 + i];
        const float2 dxj = *(const float2*)(dxp + s * 8 + j0);

        const float m = fmaf(dxi, 0.16666666666666666f, S1h);
        const float n = fmaf(3.0f, m, -S1h);          // dxi/2 + S1
        const float c0 = fmaf(dxj.x, m, S20);
        const float c1 = fmaf(dxj.y, m, S21);
        S20 = fmaf(dxj.x, n, S20);
        S21 = fmaf(dxj.y, n, S21);

        S3[0][0] = fmaf(c0, d0.x, S3[0][0]);
        S3[0][1] = fmaf(c0, d0.y, S3[0][1]);
        S3[0][2] = fmaf(c0, d0.z, S3[0][2]);
        S3[0][3] = fmaf(c0, d0.w, S3[0][3]);
        S3[0][4] = fmaf(c0, d1.x, S3[0][4]);
        S3[0][5] = fmaf(c0, d1.y, S3[0][5]);
        S3[0][6] = fmaf(c0, d1.z, S3[0][6]);
        S3[0][7] = fmaf(c0, d1.w, S3[0][7]);
        S3[1][0] = fmaf(c1, d0.x, S3[1][0]);
        S3[1][1] = fmaf(c1, d0.y, S3[1][1]);
        S3[1][2] = fmaf(c1, d0.z, S3[1][2]);
        S3[1][3] = fmaf(c1, d0.w, S3[1][3]);
        S3[1][4] = fmaf(c1, d1.x, S3[1][4]);
        S3[1][5] = fmaf(c1, d1.y, S3[1][5]);
        S3[1][6] = fmaf(c1, d1.z, S3[1][6]);
        S3[1][7] = fmaf(c1, d1.w, S3[1][7]);

        S1h = fmaf(0.5f, dxi, S1h);
    }

    SigRegs S;
    S.A1 = 2.f * S1h;
    S.A2[0] = S20; S.A2[1] = S21;
    #pragma unroll
    for (int p = 0; p < 2; p++)
        #pragma unroll
        for (int k = 0; k < 8; k++) S.A3[p][k] = S3[p][k];

    // scan reads done before publish overwrites the warp's buffer
    __syncwarp();

    // ---- in-block tree fold: 4 segment sigs -> half-batch signature ----
    if (g & 1) sig_store(sdx[g], S, i, j0);
    __syncthreads();

    if ((g & 1) == 0) {
        sig_fold(S, sdx[g + 1], i, j0);
        if (g == 2) sig_store(sdx[2], S, i, j0);
    }
    __syncthreads();

    if (g == 0) {
        sig_fold(S, sdx[2], i, j0);

        // publish this half-batch signature
        sig_store(g_half + (size_t)blk * SIGSZ, S, i, j0);
        __threadfence();   // release: half sig visible before ticket bump
        __syncwarp();

        int ticket = 0;
        if (lane == 0) ticket = atomicAdd(&g_ticket[batch], 1);
        ticket = __shfl_sync(0xffffffffu, ticket, 0);

        // Second arrival this launch (odd ticket) folds half0 o half1 -> out.
        if (ticket & 1) {
            __threadfence();   // acquire: see the peer block's half sig
            const float* pa = g_half + (size_t)batch * 2 * SIGSZ;
            SigRegs F;
            sig_load_cg(F, pa, i, j0);            // half 0
            sig_fold_cg(F, pa + SIGSZ, i, j0);    // o half 1

            float* __restrict__ ob = out + (size_t)batch * SIGSZ;
            if (j0 == 0) ob[i] = F.A1;
            *(float2*)(ob + 8 + i * 8 + j0) = make_float2(F.A2[0], F.A2[1]);
            float* b3 = ob + 72 + (i * 8 + j0) * 8;
            *(float4*)(b3)      = make_float4(F.A3[0][0], F.A3[0][1], F.A3[0][2], F.A3[0][3]);
            *(float4*)(b3 + 4)  = make_float4(F.A3[0][4], F.A3[0][5], F.A3[0][6], F.A3[0][7]);
            *(float4*)(b3 + 8)  = make_float4(F.A3[1][0], F.A3[1][1], F.A3[1][2], F.A3[1][3]);
            *(float4*)(b3 + 12) = make_float4(F.A3[1][4], F.A3[1][5], F.A3[1][6], F.A3[1][7]);
        }
    }
}

extern "C" void kernel_launch(void* const* d_in, const int* in_sizes, int n_in,
                              void* d_out, int out_size) {
    const float* path = (const float*)d_in[0];
    float* out = (float*)d_out;
    sig_kernel<<<NB * 2, 128>>>(path, out);   // single fused launch
}